// round 11
// baseline (speedup 1.0000x reference)
#include <cuda_runtime.h>
#include <cuda_fp16.h>
#include <math.h>

#define Bb   16
#define Ss   1024
#define FEAT 10
#define HID  128
#define HEADS 4
#define DH   32
#define LL   2
#define FF   256
#define BSZ  64
#define NB   16
#define NROWS (Bb*Ss)        // 16384

// ---- scratch ----
__device__ float  g_h[NROWS*HID];          // fp32 master residual stream
__device__ __half g_hh[NROWS*HID];         // fp16 mirror of h
__device__ __half g_qh[NROWS*HID];
__device__ __half g_kh[NROWS*HID];
__device__ __half g_vh[NROWS*HID];
__device__ __half g_ctxh[NROWS*HID];
__device__ __half g_ffh[NROWS*FF];
__device__ int    g_bcnt[NB];
__device__ int    g_blist[NB*NB];
// fp16 fragment-order weights
__device__ unsigned g_wqkv[LL*3*8192];
__device__ unsigned g_wo  [LL*8192];
__device__ unsigned g_w1  [LL*16384];
__device__ unsigned g_w2  [LL*16384];

__device__ __forceinline__ void mma16(float* c, const unsigned* a, unsigned b0, unsigned b1) {
    asm volatile(
        "mma.sync.aligned.m16n8k16.row.col.f32.f16.f16.f32 "
        "{%0,%1,%2,%3},{%4,%5,%6,%7},{%8,%9},{%0,%1,%2,%3};"
        : "+f"(c[0]), "+f"(c[1]), "+f"(c[2]), "+f"(c[3])
        : "r"(a[0]), "r"(a[1]), "r"(a[2]), "r"(a[3]), "r"(b0), "r"(b1));
}

__device__ __forceinline__ void ldsm4(unsigned& r0, unsigned& r1, unsigned& r2, unsigned& r3,
                                      const void* p) {
    unsigned a = (unsigned)__cvta_generic_to_shared(p);
    asm volatile("ldmatrix.sync.aligned.m8n8.x4.shared.b16 {%0,%1,%2,%3},[%4];"
                 : "=r"(r0), "=r"(r1), "=r"(r2), "=r"(r3) : "r"(a));
}

__device__ __forceinline__ void ldsm4t(unsigned& r0, unsigned& r1, unsigned& r2, unsigned& r3,
                                       const void* p) {
    unsigned a = (unsigned)__cvta_generic_to_shared(p);
    asm volatile("ldmatrix.sync.aligned.m8n8.x4.trans.shared.b16 {%0,%1,%2,%3},[%4];"
                 : "=r"(r0), "=r"(r1), "=r"(r2), "=r"(r3) : "r"(a));
}

__device__ __forceinline__ void cpa16(void* smem_dst, const void* gsrc) {
    unsigned d = (unsigned)__cvta_generic_to_shared(smem_dst);
    asm volatile("cp.async.cg.shared.global [%0],[%1],16;\n" :: "r"(d), "l"(gsrc));
}
__device__ __forceinline__ void cpa_commit() { asm volatile("cp.async.commit_group;\n"); }
template <int N>
__device__ __forceinline__ void cpa_wait() { asm volatile("cp.async.wait_group %0;\n" :: "n"(N)); }

// ---- block mask -> per-qb active kb list ----
__global__ void bmask_kernel(const unsigned char* __restrict__ mask) {
    int t = threadIdx.x;
    if (t < NB) {
        int c = 0;
        for (int kb = 0; kb < NB; kb++) {
            if (mask[(size_t)(t * BSZ) * Ss + kb * BSZ]) g_blist[t * NB + c++] = kb;
        }
        g_bcnt[t] = c;
    }
}

// ---- weight convert to fp16 fragment order ----
__global__ void wconv_kernel(const float* __restrict__ Wq, const float* __restrict__ Wk,
                             const float* __restrict__ Wv, const float* __restrict__ Wo,
                             const float* __restrict__ W1, const float* __restrict__ W2) {
    int m = blockIdx.y;
    int l = m / 6, t = m % 6;
    int words = (t >= 4) ? 16384 : 8192;
    int i = blockIdx.x * 256 + threadIdx.x;
    if (i >= words) return;
    const float* src; unsigned* dst; int Kd, ldn;
    switch (t) {
        case 0: src = Wq + (size_t)l*16384; dst = g_wqkv + (size_t)l*24576;         Kd = 128; ldn = 128; break;
        case 1: src = Wk + (size_t)l*16384; dst = g_wqkv + (size_t)l*24576 + 8192;  Kd = 128; ldn = 128; break;
        case 2: src = Wv + (size_t)l*16384; dst = g_wqkv + (size_t)l*24576 + 16384; Kd = 128; ldn = 128; break;
        case 3: src = Wo + (size_t)l*16384; dst = g_wo + (size_t)l*8192;            Kd = 128; ldn = 128; break;
        case 4: src = W1 + (size_t)l*32768; dst = g_w1 + (size_t)l*16384;           Kd = 128; ldn = 256; break;
        default:src = W2 + (size_t)l*32768; dst = g_w2 + (size_t)l*16384;           Kd = 256; ldn = 128; break;
    }
    int ws = Kd * 64;            // words per 128-col slice
    int slice = i / ws, j = i % ws;
    int q = j & 3, lane = (j >> 2) & 31, blk = j >> 7;
    int nt = blk & 15, ch = blk >> 4;
    int kc = ch * 2 + (q >> 1);
    int k = kc * 16 + (q & 1) * 8 + (lane & 3) * 2;
    int n = slice * 128 + nt * 8 + (lane >> 2);
    __half2 hv = __floats2half2_rn(src[(size_t)k * ldn + n], src[(size_t)(k + 1) * ldn + n]);
    dst[i] = *(unsigned*)&hv;
}

// ---- embedding + LN: warp per row, shuffle-only reduction ----
__global__ void __launch_bounds__(256) embed_kernel(
        const float* __restrict__ x,
        const float* __restrict__ tw,
        const float* __restrict__ tb,
        const float* __restrict__ pos,
        const float* __restrict__ mpos,
        const float* __restrict__ type_e,
        const float* __restrict__ lns,
        const float* __restrict__ lnb) {
    int warp = threadIdx.x >> 5, lane = threadIdx.x & 31;
    int row = blockIdx.x * 8 + warp;
    int s = row & (Ss - 1);
    int col = lane * 4;
    float xv[FEAT];
    const float* xr = x + (size_t)row * FEAT;
    #pragma unroll
    for (int f = 0; f < FEAT; f++) xv[f] = xr[f];
    float v[4];
    #pragma unroll
    for (int j = 0; j < 4; j++) {
        int cj = col + j;
        v[j] = tb[cj] + pos[s * HID + cj] + mpos[s * HID + cj] + type_e[cj];
        #pragma unroll
        for (int f = 0; f < FEAT; f++) v[j] = fmaf(xv[f], tw[f * HID + cj], v[j]);
    }
    float sm = v[0] + v[1] + v[2] + v[3];
    float sq = v[0]*v[0] + v[1]*v[1] + v[2]*v[2] + v[3]*v[3];
    #pragma unroll
    for (int o = 16; o > 0; o >>= 1) {
        sm += __shfl_xor_sync(0xFFFFFFFFu, sm, o);
        sq += __shfl_xor_sync(0xFFFFFFFFu, sq, o);
    }
    float mu = sm * (1.0f / HID);
    float rstd = rsqrtf(sq * (1.0f / HID) - mu * mu + 1e-12f);
    float4 o4;
    float* ov = (float*)&o4;
    #pragma unroll
    for (int j = 0; j < 4; j++) ov[j] = (v[j] - mu) * rstd * lns[col + j] + lnb[col + j];
    *(float4*)&g_h[(size_t)row * HID + col] = o4;
    *(__half2*)&g_hh[(size_t)row * HID + col] = __floats2half2_rn(o4.x, o4.y);
    *(__half2*)&g_hh[(size_t)row * HID + col + 2] = __floats2half2_rn(o4.z, o4.w);
}

// ---- fp16 GEMM: CTA = 64 rows x 128 cols, K chunked by 32 ----
// 3-stage cp.async ring with wait<1>: stall per chunk ~ latency - 2*compute.
// warps 2(row) x 4(col); warp tile 32 rows x 32 cols; ~42 KB static smem, 3 CTAs/SM.
// EPI: 0 = qkv->half (q scaled), 1 = quickGELU->g_ffh, 2 = residual+LN->g_h+g_hh (+optional out)
// SRC: 0 = g_hh, 1 = g_ctxh, 2 = g_ffh
template <int K, int EPI, int SRC>
__global__ void __launch_bounds__(256, 3) gemm_kernel(
        int l, float scale,
        const float* __restrict__ bias0, const float* __restrict__ bias1,
        const float* __restrict__ bias2,
        const float* __restrict__ lns, const float* __restrict__ lnb,
        float* __restrict__ outp) {
    constexpr int NCH = K / 32;
    __shared__ __half xs[3][64][40];
    __shared__ uint4 sB[3][512];
    __shared__ float2 sred[64][4];

    const __half* act = (SRC == 0) ? g_hh : (SRC == 1) ? g_ctxh : g_ffh;
    int slice = blockIdx.y;
    const unsigned* wf;
    if (EPI == 0)      wf = g_wqkv + (size_t)l * 24576 + slice * 8192;
    else if (EPI == 1) wf = g_w1 + (size_t)l * 16384 + slice * 8192;
    else               wf = (SRC == 1) ? (g_wo + (size_t)l * 8192) : (g_w2 + (size_t)l * 16384);
    const uint4* wf4 = (const uint4*)wf;

    int row0 = blockIdx.x * 64;
    int tid = threadIdx.x;
    int w = tid >> 5, lane = tid & 31;
    int wrow = w & 1, wcol = w >> 1;
    int lr = lane >> 2, lc = lane & 3;

    auto prefetch = [&](int ch, int buf) {
        {   // 256 x 16B activations (64 rows x 32 k)
            int r = tid >> 2, sg = tid & 3;
            cpa16(&xs[buf][r][sg * 8], &act[(size_t)(row0 + r) * K + ch * 32 + sg * 8]);
        }
        #pragma unroll
        for (int i = 0; i < 2; i++) {  // 512 x 16B weights (128 n x 32 k)
            int idx = tid + i * 256;
            cpa16(&sB[buf][idx], &wf4[(size_t)ch * 512 + idx]);
        }
        cpa_commit();
    };

    float acc[2][4][4];
    #pragma unroll
    for (int rb = 0; rb < 2; rb++)
        #pragma unroll
        for (int nt = 0; nt < 4; nt++) {
            int col = (wcol * 4 + nt) * 8 + 2 * lc;
            const float* bp = (EPI == 0) ? ((slice == 0) ? bias0 : (slice == 1) ? bias1 : bias2)
                             : (EPI == 1) ? bias0 + slice * 128 : bias0;
            float2 b2 = *(const float2*)&bp[col];
            acc[rb][nt][0] = b2.x; acc[rb][nt][1] = b2.y;
            acc[rb][nt][2] = b2.x; acc[rb][nt][3] = b2.y;
        }

    prefetch(0, 0);
    if (NCH > 1) prefetch(1, 1);
    #pragma unroll
    for (int ch = 0; ch < NCH; ch++) {
        int buf = ch % 3;
        if (ch + 1 < NCH) cpa_wait<1>();
        else              cpa_wait<0>();
        __syncthreads();
        if (ch + 2 < NCH) prefetch(ch + 2, (ch + 2) % 3);

        unsigned aF[2][2][4];
        #pragma unroll
        for (int rb = 0; rb < 2; rb++)
            #pragma unroll
            for (int kp = 0; kp < 2; kp++)
                ldsm4(aF[rb][kp][0], aF[rb][kp][1], aF[rb][kp][2], aF[rb][kp][3],
                      &xs[buf][wrow * 32 + rb * 16 + (lane & 15)][kp * 16 + (lane >> 4) * 8]);
        #pragma unroll
        for (int nt = 0; nt < 4; nt++) {
            uint4 wv = sB[buf][(wcol * 4 + nt) * 32 + lane];
            #pragma unroll
            for (int rb = 0; rb < 2; rb++) {
                mma16(acc[rb][nt], aF[rb][0], wv.x, wv.y);
                mma16(acc[rb][nt], aF[rb][1], wv.z, wv.w);
            }
        }
    }

    if (EPI == 0) {
        __half* dst = (slice == 0) ? g_qh : (slice == 1) ? g_kh : g_vh;
        float s = (slice == 0) ? scale : 1.0f;
        #pragma unroll
        for (int rb = 0; rb < 2; rb++) {
            int r = row0 + wrow * 32 + rb * 16 + lr;
            #pragma unroll
            for (int nt = 0; nt < 4; nt++) {
                int col = (wcol * 4 + nt) * 8 + 2 * lc;
                *(__half2*)&dst[(size_t)r * HID + col] =
                    __floats2half2_rn(acc[rb][nt][0] * s, acc[rb][nt][1] * s);
                *(__half2*)&dst[(size_t)(r + 8) * HID + col] =
                    __floats2half2_rn(acc[rb][nt][2] * s, acc[rb][nt][3] * s);
            }
        }
    } else if (EPI == 1) {
        #pragma unroll
        for (int rb = 0; rb < 2; rb++) {
            int r = row0 + wrow * 32 + rb * 16 + lr;
            #pragma unroll
            for (int nt = 0; nt < 4; nt++) {
                int gcol = slice * 128 + (wcol * 4 + nt) * 8 + 2 * lc;
                float a0 = acc[rb][nt][0], a1 = acc[rb][nt][1];
                float a2 = acc[rb][nt][2], a3 = acc[rb][nt][3];
                a0 = a0 / (1.0f + __expf(-1.702f * a0));
                a1 = a1 / (1.0f + __expf(-1.702f * a1));
                a2 = a2 / (1.0f + __expf(-1.702f * a2));
                a3 = a3 / (1.0f + __expf(-1.702f * a3));
                *(__half2*)&g_ffh[(size_t)r * FF + gcol] = __floats2half2_rn(a0, a1);
                *(__half2*)&g_ffh[(size_t)(r + 8) * FF + gcol] = __floats2half2_rn(a2, a3);
            }
        }
    } else {
        #pragma unroll
        for (int rb = 0; rb < 2; rb++) {
            int r = row0 + wrow * 32 + rb * 16 + lr;
            float s0 = 0.f, q0 = 0.f, s1 = 0.f, q1 = 0.f;
            #pragma unroll
            for (int nt = 0; nt < 4; nt++) {
                int col = (wcol * 4 + nt) * 8 + 2 * lc;
                float2 h0 = *(const float2*)&g_h[(size_t)r * HID + col];
                float2 h1 = *(const float2*)&g_h[(size_t)(r + 8) * HID + col];
                float a0 = acc[rb][nt][0] + h0.x, a1 = acc[rb][nt][1] + h0.y;
                float a2 = acc[rb][nt][2] + h1.x, a3 = acc[rb][nt][3] + h1.y;
                acc[rb][nt][0] = a0; acc[rb][nt][1] = a1;
                acc[rb][nt][2] = a2; acc[rb][nt][3] = a3;
                s0 += a0 + a1; q0 += a0 * a0 + a1 * a1;
                s1 += a2 + a3; q1 += a2 * a2 + a3 * a3;
            }
            #pragma unroll
            for (int o = 1; o <= 2; o <<= 1) {
                s0 += __shfl_xor_sync(0xFFFFFFFFu, s0, o);
                q0 += __shfl_xor_sync(0xFFFFFFFFu, q0, o);
                s1 += __shfl_xor_sync(0xFFFFFFFFu, s1, o);
                q1 += __shfl_xor_sync(0xFFFFFFFFu, q1, o);
            }
            if (lc == 0) {
                int lrow = wrow * 32 + rb * 16 + lr;
                sred[lrow][wcol] = make_float2(s0, q0);
                sred[lrow + 8][wcol] = make_float2(s1, q1);
            }
        }
        __syncthreads();
        #pragma unroll
        for (int rb = 0; rb < 2; rb++) {
            int lrow = wrow * 32 + rb * 16 + lr;
            int r = row0 + lrow;
            float2 t0 = sred[lrow][0], t1 = sred[lrow][1];
            float2 t2 = sred[lrow][2], t3 = sred[lrow][3];
            float S0 = t0.x + t1.x + t2.x + t3.x, Q0 = t0.y + t1.y + t2.y + t3.y;
            float2 u0 = sred[lrow + 8][0], u1 = sred[lrow + 8][1];
            float2 u2 = sred[lrow + 8][2], u3 = sred[lrow + 8][3];
            float S1 = u0.x + u1.x + u2.x + u3.x, Q1 = u0.y + u1.y + u2.y + u3.y;
            float mu0 = S0 * (1.0f / HID);
            float rs0 = rsqrtf(Q0 * (1.0f / HID) - mu0 * mu0 + 1e-12f);
            float mu1 = S1 * (1.0f / HID);
            float rs1 = rsqrtf(Q1 * (1.0f / HID) - mu1 * mu1 + 1e-12f);
            #pragma unroll
            for (int nt = 0; nt < 4; nt++) {
                int col = (wcol * 4 + nt) * 8 + 2 * lc;
                float2 sc = *(const float2*)&lns[col];
                float2 bb = *(const float2*)&lnb[col];
                float o0x = (acc[rb][nt][0] - mu0) * rs0 * sc.x + bb.x;
                float o0y = (acc[rb][nt][1] - mu0) * rs0 * sc.y + bb.y;
                float o1x = (acc[rb][nt][2] - mu1) * rs1 * sc.x + bb.x;
                float o1y = (acc[rb][nt][3] - mu1) * rs1 * sc.y + bb.y;
                *(float2*)&g_h[(size_t)r * HID + col] = make_float2(o0x, o0y);
                *(float2*)&g_h[(size_t)(r + 8) * HID + col] = make_float2(o1x, o1y);
                *(__half2*)&g_hh[(size_t)r * HID + col] = __floats2half2_rn(o0x, o0y);
                *(__half2*)&g_hh[(size_t)(r + 8) * HID + col] = __floats2half2_rn(o1x, o1y);
                if (outp) {
                    if ((r & (Ss - 1)) == Ss - 1)
                        *(float2*)&outp[(r >> 10) * HID + col] = make_float2(o0x, o0y);
                    if (((r + 8) & (Ss - 1)) == Ss - 1)
                        *(float2*)&outp[((r + 8) >> 10) * HID + col] = make_float2(o1x, o1y);
                }
            }
        }
    }
}

// ---- FA2-style fp16 attention, 3-stage ring over KV blocks, direct ctx write ----
__global__ void __launch_bounds__(128) attn_kernel() {
    __shared__ __half sK[3][64][40];
    __shared__ __half sV[3][64][40];

    int qb = blockIdx.x, bh = blockIdx.y;
    int b = bh >> 2, h = bh & 3;
    int tid = threadIdx.x;
    int w = tid >> 5, lane = tid & 31;
    int lr = lane >> 2, lc = lane & 3;

    unsigned qf[2][4];
    {
        const __half* qp = g_qh + (size_t)(b * Ss + qb * BSZ + w * 16) * HID + h * DH;
        #pragma unroll
        for (int kc = 0; kc < 2; kc++) {
            qf[kc][0] = *(const unsigned*)&qp[(size_t)lr * HID + kc * 16 + 2 * lc];
            qf[kc][1] = *(const unsigned*)&qp[(size_t)(lr + 8) * HID + kc * 16 + 2 * lc];
            qf[kc][2] = *(const unsigned*)&qp[(size_t)lr * HID + kc * 16 + 2 * lc + 8];
            qf[kc][3] = *(const unsigned*)&qp[(size_t)(lr + 8) * HID + kc * 16 + 2 * lc + 8];
        }
    }

    float o[4][4];
    #pragma unroll
    for (int i = 0; i < 4; i++)
        #pragma unroll
        for (int j = 0; j < 4; j++) o[i][j] = 0.f;
    float ls0 = 0.f, ls1 = 0.f;

    int cnt = g_bcnt[qb];

    auto prefetch = [&](int ii, int buf) {
        int kb = g_blist[qb * NB + ii];
        #pragma unroll
        for (int i = 0; i < 4; i++) {
            int idx = tid + i * 128;          // 512 x 16B (K then V)
            int kv = idx >> 8;
            int r = (idx >> 2) & 63, seg = idx & 3;
            const __half* src = (kv ? g_vh : g_kh) +
                (size_t)(b * Ss + kb * BSZ + r) * HID + h * DH + seg * 8;
            cpa16(kv ? &sV[buf][r][seg * 8] : &sK[buf][r][seg * 8], src);
        }
        cpa_commit();
    };

    prefetch(0, 0);
    if (cnt > 1) prefetch(1, 1);
    for (int ii = 0; ii < cnt; ii++) {
        int s = ii % 3;
        if (ii + 1 < cnt) cpa_wait<1>();
        else              cpa_wait<0>();
        __syncthreads();
        if (ii + 2 < cnt) prefetch(ii + 2, (ii + 2) % 3);

        float sc[8][4];
        #pragma unroll
        for (int nc = 0; nc < 8; nc++) {
            sc[nc][0] = 0.f; sc[nc][1] = 0.f; sc[nc][2] = 0.f; sc[nc][3] = 0.f;
            unsigned r0, r1, r2, r3;
            ldsm4(r0, r1, r2, r3, &sK[s][nc * 8 + (lane & 7)][(lane >> 3) * 8]);
            mma16(sc[nc], qf[0], r0, r1);
            mma16(sc[nc], qf[1], r2, r3);
        }
        #pragma unroll
        for (int kc2 = 0; kc2 < 4; kc2++) {
            float e00 = __expf(sc[2*kc2][0]),   e01 = __expf(sc[2*kc2][1]);
            float e02 = __expf(sc[2*kc2][2]),   e03 = __expf(sc[2*kc2][3]);
            float e10 = __expf(sc[2*kc2+1][0]), e11 = __expf(sc[2*kc2+1][1]);
            float e12 = __expf(sc[2*kc2+1][2]), e13 = __expf(sc[2*kc2+1][3]);
            ls0 += e00 + e01 + e10 + e11;
            ls1 += e02 + e03 + e12 + e13;
            unsigned pf[4];
            __half2 p0 = __floats2half2_rn(e00, e01);
            __half2 p1 = __floats2half2_rn(e02, e03);
            __half2 p2 = __floats2half2_rn(e10, e11);
            __half2 p3 = __floats2half2_rn(e12, e13);
            pf[0] = *(unsigned*)&p0; pf[1] = *(unsigned*)&p1;
            pf[2] = *(unsigned*)&p2; pf[3] = *(unsigned*)&p3;
            unsigned r0, r1, r2, r3;
            const __half* vbase = &sV[s][kc2 * 16 + ((lane >> 3) & 1) * 8 + (lane & 7)][0];
            ldsm4t(r0, r1, r2, r3, vbase + (lane >> 4) * 8);
            mma16(o[0], pf, r0, r1);
            mma16(o[1], pf, r2, r3);
            ldsm4t(r0, r1, r2, r3, vbase + (lane >> 4) * 8 + 16);
            mma16(o[2], pf, r0, r1);
            mma16(o[3], pf, r2, r3);
        }
    }

    ls0 += __shfl_xor_sync(0xFFFFFFFFu, ls0, 1);
    ls0 += __shfl_xor_sync(0xFFFFFFFFu, ls0, 2);
    ls1 += __shfl_xor_sync(0xFFFFFFFFu, ls1, 1);
    ls1 += __shfl_xor_sync(0xFFFFFFFFu, ls1, 2);
    float inv0 = 1.0f / ls0, inv1 = 1.0f / ls1;

    int r0 = b * Ss + qb * BSZ + w * 16 + lr;
    __half* c0 = &g_ctxh[(size_t)r0 * HID + h * DH];
    __half* c1 = &g_ctxh[(size_t)(r0 + 8) * HID + h * DH];
    #pragma unroll
    for (int nt = 0; nt < 4; nt++) {
        *(__half2*)&c0[nt * 8 + 2 * lc] = __floats2half2_rn(o[nt][0] * inv0, o[nt][1] * inv0);
        *(__half2*)&c1[nt * 8 + 2 * lc] = __floats2half2_rn(o[nt][2] * inv1, o[nt][3] * inv1);
    }
}

extern "C" void kernel_launch(void* const* d_in, const int* in_sizes, int n_in,
                              void* d_out, int out_size) {
    const float* x       = (const float*)d_in[0];
    const float* token_w = (const float*)d_in[1];
    const float* token_b = (const float*)d_in[2];
    const float* pos_emb = (const float*)d_in[3];
    const float* mpos    = (const float*)d_in[4];
    const float* type_e  = (const float*)d_in[5];
    const float* elns    = (const float*)d_in[6];
    const float* elnb    = (const float*)d_in[7];
    const float* Wq      = (const float*)d_in[8];
    const float* bq      = (const float*)d_in[9];
    const float* Wk      = (const float*)d_in[10];
    const float* bk      = (const float*)d_in[11];
    const float* Wv      = (const float*)d_in[12];
    const float* bv      = (const float*)d_in[13];
    const float* Wo      = (const float*)d_in[14];
    const float* bo      = (const float*)d_in[15];
    const float* ln1s    = (const float*)d_in[16];
    const float* ln1b    = (const float*)d_in[17];
    const float* W1      = (const float*)d_in[18];
    const float* b1      = (const float*)d_in[19];
    const float* W2      = (const float*)d_in[20];
    const float* b2      = (const float*)d_in[21];
    const float* ln2s    = (const float*)d_in[22];
    const float* ln2b    = (const float*)d_in[23];
    const unsigned char* mask = (const unsigned char*)d_in[24];

    bmask_kernel<<<1, 32>>>(mask);
    wconv_kernel<<<dim3(64, 6 * LL), 256>>>(Wq, Wk, Wv, Wo, W1, W2);
    embed_kernel<<<NROWS / 8, 256>>>(x, token_w, token_b, pos_emb, mpos, type_e, elns, elnb);

    const float scale = 1.0f / sqrtf((float)DH);
    for (int l = 0; l < LL; l++) {
        gemm_kernel<128, 0, 0><<<dim3(NROWS / 64, 3), 256>>>(
            l, scale, bq + l * HID, bk + l * HID, bv + l * HID, 0, 0, 0);
        attn_kernel<<<dim3(NB, Bb * HEADS), 128>>>();
        gemm_kernel<128, 2, 1><<<dim3(NROWS / 64, 1), 256>>>(
            l, 1.f, bo + l * HID, 0, 0, ln1s + l * HID, ln1b + l * HID, 0);
        gemm_kernel<128, 1, 0><<<dim3(NROWS / 64, 2), 256>>>(
            l, 1.f, b1 + l * FF, 0, 0, 0, 0, 0);
        gemm_kernel<256, 2, 2><<<dim3(NROWS / 64, 1), 256>>>(
            l, 1.f, b2 + l * HID, 0, 0, ln2s + l * HID, ln2b + l * HID,
            (l == LL - 1) ? (float*)d_out : 0);
    }
}

// round 12
// speedup vs baseline: 1.0594x; 1.0594x over previous
#include <cuda_runtime.h>
#include <cuda_fp16.h>
#include <math.h>

#define Bb   16
#define Ss   1024
#define FEAT 10
#define HID  128
#define HEADS 4
#define DH   32
#define LL   2
#define FF   256
#define BSZ  64
#define NB   16
#define NROWS (Bb*Ss)        // 16384

// ---- scratch ----
__device__ float  g_h[NROWS*HID];
__device__ __half g_hh[NROWS*HID];
__device__ __half g_qh[NROWS*HID];
__device__ __half g_kh[NROWS*HID];
__device__ __half g_vh[NROWS*HID];
__device__ __half g_ctxh[NROWS*HID];
__device__ __half g_ffh[NROWS*FF];
__device__ int    g_bcnt[NB];
__device__ int    g_blist[NB*NB];
__device__ unsigned g_wqkv[LL*3*8192];
__device__ unsigned g_wo  [LL*8192];
__device__ unsigned g_w1  [LL*16384];
__device__ unsigned g_w2  [LL*16384];

__device__ __forceinline__ void mma16(float* c, const unsigned* a, unsigned b0, unsigned b1) {
    asm volatile(
        "mma.sync.aligned.m16n8k16.row.col.f32.f16.f16.f32 "
        "{%0,%1,%2,%3},{%4,%5,%6,%7},{%8,%9},{%0,%1,%2,%3};"
        : "+f"(c[0]), "+f"(c[1]), "+f"(c[2]), "+f"(c[3])
        : "r"(a[0]), "r"(a[1]), "r"(a[2]), "r"(a[3]), "r"(b0), "r"(b1));
}

__device__ __forceinline__ void ldsm4(unsigned& r0, unsigned& r1, unsigned& r2, unsigned& r3,
                                      const void* p) {
    unsigned a = (unsigned)__cvta_generic_to_shared(p);
    asm volatile("ldmatrix.sync.aligned.m8n8.x4.shared.b16 {%0,%1,%2,%3},[%4];"
                 : "=r"(r0), "=r"(r1), "=r"(r2), "=r"(r3) : "r"(a));
}

__device__ __forceinline__ void ldsm4t(unsigned& r0, unsigned& r1, unsigned& r2, unsigned& r3,
                                       const void* p) {
    unsigned a = (unsigned)__cvta_generic_to_shared(p);
    asm volatile("ldmatrix.sync.aligned.m8n8.x4.trans.shared.b16 {%0,%1,%2,%3},[%4];"
                 : "=r"(r0), "=r"(r1), "=r"(r2), "=r"(r3) : "r"(a));
}

__device__ __forceinline__ void cpa16(void* smem_dst, const void* gsrc) {
    unsigned d = (unsigned)__cvta_generic_to_shared(smem_dst);
    asm volatile("cp.async.cg.shared.global [%0],[%1],16;\n" :: "r"(d), "l"(gsrc));
}
__device__ __forceinline__ void cpa_commit() { asm volatile("cp.async.commit_group;\n"); }
template <int N>
__device__ __forceinline__ void cpa_wait() { asm volatile("cp.async.wait_group %0;\n" :: "n"(N)); }

// ---- weight convert to fp16 fragment order; bmask folded into one block ----
__global__ void wconv_kernel(const float* __restrict__ Wq, const float* __restrict__ Wk,
                             const float* __restrict__ Wv, const float* __restrict__ Wo,
                             const float* __restrict__ W1, const float* __restrict__ W2,
                             const unsigned char* __restrict__ mask) {
    int m = blockIdx.y;
    int l = m / 6, t = m % 6;

    // fold bmask into the first block of the first weight
    if (m == 0 && blockIdx.x == 0 && threadIdx.x >= 224) {
        int qb = threadIdx.x - 224;
        if (qb < NB) {
            int c = 0;
            for (int kb = 0; kb < NB; kb++) {
                if (mask[(size_t)(qb * BSZ) * Ss + kb * BSZ]) g_blist[qb * NB + c++] = kb;
            }
            g_bcnt[qb] = c;
        }
    }

    int words = (t >= 4) ? 16384 : 8192;
    int i = blockIdx.x * 224 + (threadIdx.x < 224 ? threadIdx.x : -1);
    if (threadIdx.x >= 224 || i >= words) return;
    const float* src; unsigned* dst; int Kd, ldn;
    switch (t) {
        case 0: src = Wq + (size_t)l*16384; dst = g_wqkv + (size_t)l*24576;         Kd = 128; ldn = 128; break;
        case 1: src = Wk + (size_t)l*16384; dst = g_wqkv + (size_t)l*24576 + 8192;  Kd = 128; ldn = 128; break;
        case 2: src = Wv + (size_t)l*16384; dst = g_wqkv + (size_t)l*24576 + 16384; Kd = 128; ldn = 128; break;
        case 3: src = Wo + (size_t)l*16384; dst = g_wo + (size_t)l*8192;            Kd = 128; ldn = 128; break;
        case 4: src = W1 + (size_t)l*32768; dst = g_w1 + (size_t)l*16384;           Kd = 128; ldn = 256; break;
        default:src = W2 + (size_t)l*32768; dst = g_w2 + (size_t)l*16384;           Kd = 256; ldn = 128; break;
    }
    int ws = Kd * 64;
    int slice = i / ws, j = i % ws;
    int q = j & 3, lane = (j >> 2) & 31, blk = j >> 7;
    int nt = blk & 15, ch = blk >> 4;
    int kc = ch * 2 + (q >> 1);
    int k = kc * 16 + (q & 1) * 8 + (lane & 3) * 2;
    int n = slice * 128 + nt * 8 + (lane >> 2);
    __half2 hv = __floats2half2_rn(src[(size_t)k * ldn + n], src[(size_t)(k + 1) * ldn + n]);
    dst[i] = *(unsigned*)&hv;
}

// ---- embedding + LN: warp per row ----
__global__ void __launch_bounds__(256) embed_kernel(
        const float* __restrict__ x,
        const float* __restrict__ tw,
        const float* __restrict__ tb,
        const float* __restrict__ pos,
        const float* __restrict__ mpos,
        const float* __restrict__ type_e,
        const float* __restrict__ lns,
        const float* __restrict__ lnb) {
    int warp = threadIdx.x >> 5, lane = threadIdx.x & 31;
    int row = blockIdx.x * 8 + warp;
    int s = row & (Ss - 1);
    int col = lane * 4;
    float xv[FEAT];
    const float* xr = x + (size_t)row * FEAT;
    #pragma unroll
    for (int f = 0; f < FEAT; f++) xv[f] = xr[f];
    float v[4];
    #pragma unroll
    for (int j = 0; j < 4; j++) {
        int cj = col + j;
        v[j] = tb[cj] + pos[s * HID + cj] + mpos[s * HID + cj] + type_e[cj];
        #pragma unroll
        for (int f = 0; f < FEAT; f++) v[j] = fmaf(xv[f], tw[f * HID + cj], v[j]);
    }
    float sm = v[0] + v[1] + v[2] + v[3];
    float sq = v[0]*v[0] + v[1]*v[1] + v[2]*v[2] + v[3]*v[3];
    #pragma unroll
    for (int o = 16; o > 0; o >>= 1) {
        sm += __shfl_xor_sync(0xFFFFFFFFu, sm, o);
        sq += __shfl_xor_sync(0xFFFFFFFFu, sq, o);
    }
    float mu = sm * (1.0f / HID);
    float rstd = rsqrtf(sq * (1.0f / HID) - mu * mu + 1e-12f);
    float4 o4;
    float* ov = (float*)&o4;
    #pragma unroll
    for (int j = 0; j < 4; j++) ov[j] = (v[j] - mu) * rstd * lns[col + j] + lnb[col + j];
    *(float4*)&g_h[(size_t)row * HID + col] = o4;
    *(__half2*)&g_hh[(size_t)row * HID + col] = __floats2half2_rn(o4.x, o4.y);
    *(__half2*)&g_hh[(size_t)row * HID + col + 2] = __floats2half2_rn(o4.z, o4.w);
}

// ---- fp16 GEMM: 64 rows x 128 cols, 3-stage cp.async ring, wait<1> ----
template <int K, int EPI, int SRC>
__global__ void __launch_bounds__(256, 3) gemm_kernel(
        int l, float scale,
        const float* __restrict__ bias0, const float* __restrict__ bias1,
        const float* __restrict__ bias2,
        const float* __restrict__ lns, const float* __restrict__ lnb,
        float* __restrict__ outp) {
    constexpr int NCH = K / 32;
    __shared__ __half xs[3][64][40];
    __shared__ uint4 sB[3][512];
    __shared__ float2 sred[64][4];

    const __half* act = (SRC == 0) ? g_hh : (SRC == 1) ? g_ctxh : g_ffh;
    int slice = blockIdx.y;
    const unsigned* wf;
    if (EPI == 0)      wf = g_wqkv + (size_t)l * 24576 + slice * 8192;
    else if (EPI == 1) wf = g_w1 + (size_t)l * 16384 + slice * 8192;
    else               wf = (SRC == 1) ? (g_wo + (size_t)l * 8192) : (g_w2 + (size_t)l * 16384);
    const uint4* wf4 = (const uint4*)wf;

    int row0 = blockIdx.x * 64;
    int tid = threadIdx.x;
    int w = tid >> 5, lane = tid & 31;
    int wrow = w & 1, wcol = w >> 1;
    int lr = lane >> 2, lc = lane & 3;

    auto prefetch = [&](int ch, int buf) {
        {
            int r = tid >> 2, sg = tid & 3;
            cpa16(&xs[buf][r][sg * 8], &act[(size_t)(row0 + r) * K + ch * 32 + sg * 8]);
        }
        #pragma unroll
        for (int i = 0; i < 2; i++) {
            int idx = tid + i * 256;
            cpa16(&sB[buf][idx], &wf4[(size_t)ch * 512 + idx]);
        }
        cpa_commit();
    };

    float acc[2][4][4];
    #pragma unroll
    for (int rb = 0; rb < 2; rb++)
        #pragma unroll
        for (int nt = 0; nt < 4; nt++) {
            int col = (wcol * 4 + nt) * 8 + 2 * lc;
            const float* bp = (EPI == 0) ? ((slice == 0) ? bias0 : (slice == 1) ? bias1 : bias2)
                             : (EPI == 1) ? bias0 + slice * 128 : bias0;
            float2 b2 = *(const float2*)&bp[col];
            acc[rb][nt][0] = b2.x; acc[rb][nt][1] = b2.y;
            acc[rb][nt][2] = b2.x; acc[rb][nt][3] = b2.y;
        }

    prefetch(0, 0);
    if (NCH > 1) prefetch(1, 1);
    #pragma unroll
    for (int ch = 0; ch < NCH; ch++) {
        int buf = ch % 3;
        if (ch + 1 < NCH) cpa_wait<1>();
        else              cpa_wait<0>();
        __syncthreads();
        if (ch + 2 < NCH) prefetch(ch + 2, (ch + 2) % 3);

        unsigned aF[2][2][4];
        #pragma unroll
        for (int rb = 0; rb < 2; rb++)
            #pragma unroll
            for (int kp = 0; kp < 2; kp++)
                ldsm4(aF[rb][kp][0], aF[rb][kp][1], aF[rb][kp][2], aF[rb][kp][3],
                      &xs[buf][wrow * 32 + rb * 16 + (lane & 15)][kp * 16 + (lane >> 4) * 8]);
        #pragma unroll
        for (int nt = 0; nt < 4; nt++) {
            uint4 wv = sB[buf][(wcol * 4 + nt) * 32 + lane];
            #pragma unroll
            for (int rb = 0; rb < 2; rb++) {
                mma16(acc[rb][nt], aF[rb][0], wv.x, wv.y);
                mma16(acc[rb][nt], aF[rb][1], wv.z, wv.w);
            }
        }
    }

    if (EPI == 0) {
        __half* dst = (slice == 0) ? g_qh : (slice == 1) ? g_kh : g_vh;
        float s = (slice == 0) ? scale : 1.0f;
        #pragma unroll
        for (int rb = 0; rb < 2; rb++) {
            int r = row0 + wrow * 32 + rb * 16 + lr;
            #pragma unroll
            for (int nt = 0; nt < 4; nt++) {
                int col = (wcol * 4 + nt) * 8 + 2 * lc;
                *(__half2*)&dst[(size_t)r * HID + col] =
                    __floats2half2_rn(acc[rb][nt][0] * s, acc[rb][nt][1] * s);
                *(__half2*)&dst[(size_t)(r + 8) * HID + col] =
                    __floats2half2_rn(acc[rb][nt][2] * s, acc[rb][nt][3] * s);
            }
        }
    } else if (EPI == 1) {
        #pragma unroll
        for (int rb = 0; rb < 2; rb++) {
            int r = row0 + wrow * 32 + rb * 16 + lr;
            #pragma unroll
            for (int nt = 0; nt < 4; nt++) {
                int gcol = slice * 128 + (wcol * 4 + nt) * 8 + 2 * lc;
                float a0 = acc[rb][nt][0], a1 = acc[rb][nt][1];
                float a2 = acc[rb][nt][2], a3 = acc[rb][nt][3];
                a0 = a0 / (1.0f + __expf(-1.702f * a0));
                a1 = a1 / (1.0f + __expf(-1.702f * a1));
                a2 = a2 / (1.0f + __expf(-1.702f * a2));
                a3 = a3 / (1.0f + __expf(-1.702f * a3));
                *(__half2*)&g_ffh[(size_t)r * FF + gcol] = __floats2half2_rn(a0, a1);
                *(__half2*)&g_ffh[(size_t)(r + 8) * FF + gcol] = __floats2half2_rn(a2, a3);
            }
        }
    } else {
        #pragma unroll
        for (int rb = 0; rb < 2; rb++) {
            int r = row0 + wrow * 32 + rb * 16 + lr;
            float s0 = 0.f, q0 = 0.f, s1 = 0.f, q1 = 0.f;
            #pragma unroll
            for (int nt = 0; nt < 4; nt++) {
                int col = (wcol * 4 + nt) * 8 + 2 * lc;
                float2 h0 = *(const float2*)&g_h[(size_t)r * HID + col];
                float2 h1 = *(const float2*)&g_h[(size_t)(r + 8) * HID + col];
                float a0 = acc[rb][nt][0] + h0.x, a1 = acc[rb][nt][1] + h0.y;
                float a2 = acc[rb][nt][2] + h1.x, a3 = acc[rb][nt][3] + h1.y;
                acc[rb][nt][0] = a0; acc[rb][nt][1] = a1;
                acc[rb][nt][2] = a2; acc[rb][nt][3] = a3;
                s0 += a0 + a1; q0 += a0 * a0 + a1 * a1;
                s1 += a2 + a3; q1 += a2 * a2 + a3 * a3;
            }
            #pragma unroll
            for (int o = 1; o <= 2; o <<= 1) {
                s0 += __shfl_xor_sync(0xFFFFFFFFu, s0, o);
                q0 += __shfl_xor_sync(0xFFFFFFFFu, q0, o);
                s1 += __shfl_xor_sync(0xFFFFFFFFu, s1, o);
                q1 += __shfl_xor_sync(0xFFFFFFFFu, q1, o);
            }
            if (lc == 0) {
                int lrow = wrow * 32 + rb * 16 + lr;
                sred[lrow][wcol] = make_float2(s0, q0);
                sred[lrow + 8][wcol] = make_float2(s1, q1);
            }
        }
        __syncthreads();
        #pragma unroll
        for (int rb = 0; rb < 2; rb++) {
            int lrow = wrow * 32 + rb * 16 + lr;
            int r = row0 + lrow;
            float2 t0 = sred[lrow][0], t1 = sred[lrow][1];
            float2 t2 = sred[lrow][2], t3 = sred[lrow][3];
            float S0 = t0.x + t1.x + t2.x + t3.x, Q0 = t0.y + t1.y + t2.y + t3.y;
            float2 u0 = sred[lrow + 8][0], u1 = sred[lrow + 8][1];
            float2 u2 = sred[lrow + 8][2], u3 = sred[lrow + 8][3];
            float S1 = u0.x + u1.x + u2.x + u3.x, Q1 = u0.y + u1.y + u2.y + u3.y;
            float mu0 = S0 * (1.0f / HID);
            float rs0 = rsqrtf(Q0 * (1.0f / HID) - mu0 * mu0 + 1e-12f);
            float mu1 = S1 * (1.0f / HID);
            float rs1 = rsqrtf(Q1 * (1.0f / HID) - mu1 * mu1 + 1e-12f);
            #pragma unroll
            for (int nt = 0; nt < 4; nt++) {
                int col = (wcol * 4 + nt) * 8 + 2 * lc;
                float2 sc = *(const float2*)&lns[col];
                float2 bb = *(const float2*)&lnb[col];
                float o0x = (acc[rb][nt][0] - mu0) * rs0 * sc.x + bb.x;
                float o0y = (acc[rb][nt][1] - mu0) * rs0 * sc.y + bb.y;
                float o1x = (acc[rb][nt][2] - mu1) * rs1 * sc.x + bb.x;
                float o1y = (acc[rb][nt][3] - mu1) * rs1 * sc.y + bb.y;
                *(float2*)&g_h[(size_t)r * HID + col] = make_float2(o0x, o0y);
                *(float2*)&g_h[(size_t)(r + 8) * HID + col] = make_float2(o1x, o1y);
                *(__half2*)&g_hh[(size_t)r * HID + col] = __floats2half2_rn(o0x, o0y);
                *(__half2*)&g_hh[(size_t)(r + 8) * HID + col] = __floats2half2_rn(o1x, o1y);
                if (outp) {
                    if ((r & (Ss - 1)) == Ss - 1)
                        *(float2*)&outp[(r >> 10) * HID + col] = make_float2(o0x, o0y);
                    if (((r + 8) & (Ss - 1)) == Ss - 1)
                        *(float2*)&outp[((r + 8) >> 10) * HID + col] = make_float2(o1x, o1y);
                }
            }
        }
    }
}

// ---- FA2-style fp16 attention, 2-stage double buffer (best measured config) ----
__global__ void __launch_bounds__(128) attn_kernel() {
    __shared__ __half sK[2][64][40];
    __shared__ __half sV[2][64][40];

    int qb = blockIdx.x, bh = blockIdx.y;
    int b = bh >> 2, h = bh & 3;
    int tid = threadIdx.x;
    int w = tid >> 5, lane = tid & 31;
    int lr = lane >> 2, lc = lane & 3;

    unsigned qf[2][4];
    {
        const __half* qp = g_qh + (size_t)(b * Ss + qb * BSZ + w * 16) * HID + h * DH;
        #pragma unroll
        for (int kc = 0; kc < 2; kc++) {
            qf[kc][0] = *(const unsigned*)&qp[(size_t)lr * HID + kc * 16 + 2 * lc];
            qf[kc][1] = *(const unsigned*)&qp[(size_t)(lr + 8) * HID + kc * 16 + 2 * lc];
            qf[kc][2] = *(const unsigned*)&qp[(size_t)lr * HID + kc * 16 + 2 * lc + 8];
            qf[kc][3] = *(const unsigned*)&qp[(size_t)(lr + 8) * HID + kc * 16 + 2 * lc + 8];
        }
    }

    float o[4][4];
    #pragma unroll
    for (int i = 0; i < 4; i++)
        #pragma unroll
        for (int j = 0; j < 4; j++) o[i][j] = 0.f;
    float ls0 = 0.f, ls1 = 0.f;

    int cnt = g_bcnt[qb];

    auto prefetch = [&](int ii, int buf) {
        int kb = g_blist[qb * NB + ii];
        #pragma unroll
        for (int i = 0; i < 4; i++) {
            int idx = tid + i * 128;
            int kv = idx >> 8;
            int r = (idx >> 2) & 63, seg = idx & 3;
            const __half* src = (kv ? g_vh : g_kh) +
                (size_t)(b * Ss + kb * BSZ + r) * HID + h * DH + seg * 8;
            cpa16(kv ? &sV[buf][r][seg * 8] : &sK[buf][r][seg * 8], src);
        }
        cpa_commit();
    };

    prefetch(0, 0);
    for (int ii = 0; ii < cnt; ii++) {
        int s = ii & 1;
        cpa_wait<0>();
        __syncthreads();
        if (ii + 1 < cnt) prefetch(ii + 1, s ^ 1);

        float sc[8][4];
        #pragma unroll
        for (int nc = 0; nc < 8; nc++) {
            sc[nc][0] = 0.f; sc[nc][1] = 0.f; sc[nc][2] = 0.f; sc[nc][3] = 0.f;
            unsigned r0, r1, r2, r3;
            ldsm4(r0, r1, r2, r3, &sK[s][nc * 8 + (lane & 7)][(lane >> 3) * 8]);
            mma16(sc[nc], qf[0], r0, r1);
            mma16(sc[nc], qf[1], r2, r3);
        }
        #pragma unroll
        for (int kc2 = 0; kc2 < 4; kc2++) {
            float e00 = __expf(sc[2*kc2][0]),   e01 = __expf(sc[2*kc2][1]);
            float e02 = __expf(sc[2*kc2][2]),   e03 = __expf(sc[2*kc2][3]);
            float e10 = __expf(sc[2*kc2+1][0]), e11 = __expf(sc[2*kc2+1][1]);
            float e12 = __expf(sc[2*kc2+1][2]), e13 = __expf(sc[2*kc2+1][3]);
            ls0 += e00 + e01 + e10 + e11;
            ls1 += e02 + e03 + e12 + e13;
            unsigned pf[4];
            __half2 p0 = __floats2half2_rn(e00, e01);
            __half2 p1 = __floats2half2_rn(e02, e03);
            __half2 p2 = __floats2half2_rn(e10, e11);
            __half2 p3 = __floats2half2_rn(e12, e13);
            pf[0] = *(unsigned*)&p0; pf[1] = *(unsigned*)&p1;
            pf[2] = *(unsigned*)&p2; pf[3] = *(unsigned*)&p3;
            unsigned r0, r1, r2, r3;
            const __half* vbase = &sV[s][kc2 * 16 + ((lane >> 3) & 1) * 8 + (lane & 7)][0];
            ldsm4t(r0, r1, r2, r3, vbase + (lane >> 4) * 8);
            mma16(o[0], pf, r0, r1);
            mma16(o[1], pf, r2, r3);
            ldsm4t(r0, r1, r2, r3, vbase + (lane >> 4) * 8 + 16);
            mma16(o[2], pf, r0, r1);
            mma16(o[3], pf, r2, r3);
        }
    }

    ls0 += __shfl_xor_sync(0xFFFFFFFFu, ls0, 1);
    ls0 += __shfl_xor_sync(0xFFFFFFFFu, ls0, 2);
    ls1 += __shfl_xor_sync(0xFFFFFFFFu, ls1, 1);
    ls1 += __shfl_xor_sync(0xFFFFFFFFu, ls1, 2);
    float inv0 = 1.0f / ls0, inv1 = 1.0f / ls1;

    int r0 = b * Ss + qb * BSZ + w * 16 + lr;
    __half* c0 = &g_ctxh[(size_t)r0 * HID + h * DH];
    __half* c1 = &g_ctxh[(size_t)(r0 + 8) * HID + h * DH];
    #pragma unroll
    for (int nt = 0; nt < 4; nt++) {
        *(__half2*)&c0[nt * 8 + 2 * lc] = __floats2half2_rn(o[nt][0] * inv0, o[nt][1] * inv0);
        *(__half2*)&c1[nt * 8 + 2 * lc] = __floats2half2_rn(o[nt][2] * inv1, o[nt][3] * inv1);
    }
}

extern "C" void kernel_launch(void* const* d_in, const int* in_sizes, int n_in,
                              void* d_out, int out_size) {
    const float* x       = (const float*)d_in[0];
    const float* token_w = (const float*)d_in[1];
    const float* token_b = (const float*)d_in[2];
    const float* pos_emb = (const float*)d_in[3];
    const float* mpos    = (const float*)d_in[4];
    const float* type_e  = (const float*)d_in[5];
    const float* elns    = (const float*)d_in[6];
    const float* elnb    = (const float*)d_in[7];
    const float* Wq      = (const float*)d_in[8];
    const float* bq      = (const float*)d_in[9];
    const float* Wk      = (const float*)d_in[10];
    const float* bk      = (const float*)d_in[11];
    const float* Wv      = (const float*)d_in[12];
    const float* bv      = (const float*)d_in[13];
    const float* Wo      = (const float*)d_in[14];
    const float* bo      = (const float*)d_in[15];
    const float* ln1s    = (const float*)d_in[16];
    const float* ln1b    = (const float*)d_in[17];
    const float* W1      = (const float*)d_in[18];
    const float* b1      = (const float*)d_in[19];
    const float* W2      = (const float*)d_in[20];
    const float* b2      = (const float*)d_in[21];
    const float* ln2s    = (const float*)d_in[22];
    const float* ln2b    = (const float*)d_in[23];
    const unsigned char* mask = (const unsigned char*)d_in[24];

    // 224 useful convert lanes per block: ceil(16384/224) = 74 blocks covers both sizes
    wconv_kernel<<<dim3(74, 6 * LL), 256>>>(Wq, Wk, Wv, Wo, W1, W2, mask);
    embed_kernel<<<NROWS / 8, 256>>>(x, token_w, token_b, pos_emb, mpos, type_e, elns, elnb);

    const float scale = 1.0f / sqrtf((float)DH);
    for (int l = 0; l < LL; l++) {
        gemm_kernel<128, 0, 0><<<dim3(NROWS / 64, 3), 256>>>(
            l, scale, bq + l * HID, bk + l * HID, bv + l * HID, 0, 0, 0);
        attn_kernel<<<dim3(NB, Bb * HEADS), 128>>>();
        gemm_kernel<128, 2, 1><<<dim3(NROWS / 64, 1), 256>>>(
            l, 1.f, bo + l * HID, 0, 0, ln1s + l * HID, ln1b + l * HID, 0);
        gemm_kernel<128, 1, 0><<<dim3(NROWS / 64, 2), 256>>>(
            l, 1.f, b1 + l * FF, 0, 0, 0, 0, 0);
        gemm_kernel<256, 2, 2><<<dim3(NROWS / 64, 1), 256>>>(
            l, 1.f, b2 + l * HID, 0, 0, ln2s + l * HID, ln2b + l * HID,
            (l == LL - 1) ? (float*)d_out : 0);
    }
}

// round 13
// speedup vs baseline: 1.1213x; 1.0585x over previous
#include <cuda_runtime.h>
#include <cuda_fp16.h>
#include <math.h>

#define Bb   16
#define Ss   1024
#define FEAT 10
#define HID  128
#define HEADS 4
#define DH   32
#define LL   2
#define FF   256
#define BSZ  64
#define NB   16
#define NROWS (Bb*Ss)        // 16384
#define LOG2E 1.44269504088896f

// ---- scratch ----
__device__ float  g_h[NROWS*HID];
__device__ __half g_hh[NROWS*HID];
__device__ __half g_qh[NROWS*HID];
__device__ __half g_kh[NROWS*HID];
__device__ __half g_vh[NROWS*HID];
__device__ __half g_ctxh[NROWS*HID];
__device__ __half g_ffh[NROWS*FF];
__device__ int    g_bcnt[NB];
__device__ int    g_blist[NB*NB];
__device__ unsigned g_wqkv[LL*3*8192];
__device__ unsigned g_wo  [LL*8192];
__device__ unsigned g_w1  [LL*16384];
__device__ unsigned g_w2  [LL*16384];

__device__ __forceinline__ float ex2(float x) {
    float r;
    asm("ex2.approx.ftz.f32 %0, %1;" : "=f"(r) : "f"(x));
    return r;
}

__device__ __forceinline__ void mma16(float* c, const unsigned* a, unsigned b0, unsigned b1) {
    asm volatile(
        "mma.sync.aligned.m16n8k16.row.col.f32.f16.f16.f32 "
        "{%0,%1,%2,%3},{%4,%5,%6,%7},{%8,%9},{%0,%1,%2,%3};"
        : "+f"(c[0]), "+f"(c[1]), "+f"(c[2]), "+f"(c[3])
        : "r"(a[0]), "r"(a[1]), "r"(a[2]), "r"(a[3]), "r"(b0), "r"(b1));
}

__device__ __forceinline__ void ldsm4(unsigned& r0, unsigned& r1, unsigned& r2, unsigned& r3,
                                      const void* p) {
    unsigned a = (unsigned)__cvta_generic_to_shared(p);
    asm volatile("ldmatrix.sync.aligned.m8n8.x4.shared.b16 {%0,%1,%2,%3},[%4];"
                 : "=r"(r0), "=r"(r1), "=r"(r2), "=r"(r3) : "r"(a));
}

__device__ __forceinline__ void ldsm4t(unsigned& r0, unsigned& r1, unsigned& r2, unsigned& r3,
                                       const void* p) {
    unsigned a = (unsigned)__cvta_generic_to_shared(p);
    asm volatile("ldmatrix.sync.aligned.m8n8.x4.trans.shared.b16 {%0,%1,%2,%3},[%4];"
                 : "=r"(r0), "=r"(r1), "=r"(r2), "=r"(r3) : "r"(a));
}

__device__ __forceinline__ void cpa16(void* smem_dst, const void* gsrc) {
    unsigned d = (unsigned)__cvta_generic_to_shared(smem_dst);
    asm volatile("cp.async.cg.shared.global [%0],[%1],16;\n" :: "r"(d), "l"(gsrc));
}
__device__ __forceinline__ void cpa_commit() { asm volatile("cp.async.commit_group;\n"); }
template <int N>
__device__ __forceinline__ void cpa_wait() { asm volatile("cp.async.wait_group %0;\n" :: "n"(N)); }

// ---- weight convert to fp16 fragment order; bmask folded into one block ----
__global__ void wconv_kernel(const float* __restrict__ Wq, const float* __restrict__ Wk,
                             const float* __restrict__ Wv, const float* __restrict__ Wo,
                             const float* __restrict__ W1, const float* __restrict__ W2,
                             const unsigned char* __restrict__ mask) {
    int m = blockIdx.y;
    int l = m / 6, t = m % 6;

    if (m == 0 && blockIdx.x == 0 && threadIdx.x >= 224) {
        int qb = threadIdx.x - 224;
        if (qb < NB) {
            int c = 0;
            for (int kb = 0; kb < NB; kb++) {
                if (mask[(size_t)(qb * BSZ) * Ss + kb * BSZ]) g_blist[qb * NB + c++] = kb;
            }
            g_bcnt[qb] = c;
        }
    }

    int words = (t >= 4) ? 16384 : 8192;
    int i = blockIdx.x * 224 + (threadIdx.x < 224 ? threadIdx.x : -1);
    if (threadIdx.x >= 224 || i >= words) return;
    const float* src; unsigned* dst; int Kd, ldn;
    switch (t) {
        case 0: src = Wq + (size_t)l*16384; dst = g_wqkv + (size_t)l*24576;         Kd = 128; ldn = 128; break;
        case 1: src = Wk + (size_t)l*16384; dst = g_wqkv + (size_t)l*24576 + 8192;  Kd = 128; ldn = 128; break;
        case 2: src = Wv + (size_t)l*16384; dst = g_wqkv + (size_t)l*24576 + 16384; Kd = 128; ldn = 128; break;
        case 3: src = Wo + (size_t)l*16384; dst = g_wo + (size_t)l*8192;            Kd = 128; ldn = 128; break;
        case 4: src = W1 + (size_t)l*32768; dst = g_w1 + (size_t)l*16384;           Kd = 128; ldn = 256; break;
        default:src = W2 + (size_t)l*32768; dst = g_w2 + (size_t)l*16384;           Kd = 256; ldn = 128; break;
    }
    int ws = Kd * 64;
    int slice = i / ws, j = i % ws;
    int q = j & 3, lane = (j >> 2) & 31, blk = j >> 7;
    int nt = blk & 15, ch = blk >> 4;
    int kc = ch * 2 + (q >> 1);
    int k = kc * 16 + (q & 1) * 8 + (lane & 3) * 2;
    int n = slice * 128 + nt * 8 + (lane >> 2);
    __half2 hv = __floats2half2_rn(src[(size_t)k * ldn + n], src[(size_t)(k + 1) * ldn + n]);
    dst[i] = *(unsigned*)&hv;
}

// ---- embedding + LN: warp per row ----
__global__ void __launch_bounds__(256) embed_kernel(
        const float* __restrict__ x,
        const float* __restrict__ tw,
        const float* __restrict__ tb,
        const float* __restrict__ pos,
        const float* __restrict__ mpos,
        const float* __restrict__ type_e,
        const float* __restrict__ lns,
        const float* __restrict__ lnb) {
    int warp = threadIdx.x >> 5, lane = threadIdx.x & 31;
    int row = blockIdx.x * 8 + warp;
    int s = row & (Ss - 1);
    int col = lane * 4;
    float xv[FEAT];
    const float* xr = x + (size_t)row * FEAT;
    #pragma unroll
    for (int f = 0; f < FEAT; f++) xv[f] = xr[f];
    float v[4];
    #pragma unroll
    for (int j = 0; j < 4; j++) {
        int cj = col + j;
        v[j] = tb[cj] + pos[s * HID + cj] + mpos[s * HID + cj] + type_e[cj];
        #pragma unroll
        for (int f = 0; f < FEAT; f++) v[j] = fmaf(xv[f], tw[f * HID + cj], v[j]);
    }
    float sm = v[0] + v[1] + v[2] + v[3];
    float sq = v[0]*v[0] + v[1]*v[1] + v[2]*v[2] + v[3]*v[3];
    #pragma unroll
    for (int o = 16; o > 0; o >>= 1) {
        sm += __shfl_xor_sync(0xFFFFFFFFu, sm, o);
        sq += __shfl_xor_sync(0xFFFFFFFFu, sq, o);
    }
    float mu = sm * (1.0f / HID);
    float rstd = rsqrtf(sq * (1.0f / HID) - mu * mu + 1e-12f);
    float4 o4;
    float* ov = (float*)&o4;
    #pragma unroll
    for (int j = 0; j < 4; j++) ov[j] = (v[j] - mu) * rstd * lns[col + j] + lnb[col + j];
    *(float4*)&g_h[(size_t)row * HID + col] = o4;
    *(__half2*)&g_hh[(size_t)row * HID + col] = __floats2half2_rn(o4.x, o4.y);
    *(__half2*)&g_hh[(size_t)row * HID + col + 2] = __floats2half2_rn(o4.z, o4.w);
}

// ---- fp16 GEMM: 64 rows x 128 cols, 3-stage cp.async ring, wait<1> ----
template <int K, int EPI, int SRC>
__global__ void __launch_bounds__(256, 3) gemm_kernel(
        int l, float scale,
        const float* __restrict__ bias0, const float* __restrict__ bias1,
        const float* __restrict__ bias2,
        const float* __restrict__ lns, const float* __restrict__ lnb,
        float* __restrict__ outp) {
    constexpr int NCH = K / 32;
    __shared__ __half xs[3][64][40];
    __shared__ uint4 sB[3][512];
    __shared__ float2 sred[64][4];

    const __half* act = (SRC == 0) ? g_hh : (SRC == 1) ? g_ctxh : g_ffh;
    int slice = blockIdx.y;
    const unsigned* wf;
    if (EPI == 0)      wf = g_wqkv + (size_t)l * 24576 + slice * 8192;
    else if (EPI == 1) wf = g_w1 + (size_t)l * 16384 + slice * 8192;
    else               wf = (SRC == 1) ? (g_wo + (size_t)l * 8192) : (g_w2 + (size_t)l * 16384);
    const uint4* wf4 = (const uint4*)wf;

    int row0 = blockIdx.x * 64;
    int tid = threadIdx.x;
    int w = tid >> 5, lane = tid & 31;
    int wrow = w & 1, wcol = w >> 1;
    int lr = lane >> 2, lc = lane & 3;

    auto prefetch = [&](int ch, int buf) {
        {
            int r = tid >> 2, sg = tid & 3;
            cpa16(&xs[buf][r][sg * 8], &act[(size_t)(row0 + r) * K + ch * 32 + sg * 8]);
        }
        #pragma unroll
        for (int i = 0; i < 2; i++) {
            int idx = tid + i * 256;
            cpa16(&sB[buf][idx], &wf4[(size_t)ch * 512 + idx]);
        }
        cpa_commit();
    };

    // issue loads first, then fetch bias while they fly
    prefetch(0, 0);
    if (NCH > 1) prefetch(1, 1);

    float acc[2][4][4];
    #pragma unroll
    for (int rb = 0; rb < 2; rb++)
        #pragma unroll
        for (int nt = 0; nt < 4; nt++) {
            int col = (wcol * 4 + nt) * 8 + 2 * lc;
            const float* bp = (EPI == 0) ? ((slice == 0) ? bias0 : (slice == 1) ? bias1 : bias2)
                             : (EPI == 1) ? bias0 + slice * 128 : bias0;
            float2 b2 = *(const float2*)&bp[col];
            acc[rb][nt][0] = b2.x; acc[rb][nt][1] = b2.y;
            acc[rb][nt][2] = b2.x; acc[rb][nt][3] = b2.y;
        }

    #pragma unroll
    for (int ch = 0; ch < NCH; ch++) {
        int buf = ch % 3;
        if (ch + 1 < NCH) cpa_wait<1>();
        else              cpa_wait<0>();
        __syncthreads();
        if (ch + 2 < NCH) prefetch(ch + 2, (ch + 2) % 3);

        unsigned aF[2][2][4];
        #pragma unroll
        for (int rb = 0; rb < 2; rb++)
            #pragma unroll
            for (int kp = 0; kp < 2; kp++)
                ldsm4(aF[rb][kp][0], aF[rb][kp][1], aF[rb][kp][2], aF[rb][kp][3],
                      &xs[buf][wrow * 32 + rb * 16 + (lane & 15)][kp * 16 + (lane >> 4) * 8]);
        #pragma unroll
        for (int nt = 0; nt < 4; nt++) {
            uint4 wv = sB[buf][(wcol * 4 + nt) * 32 + lane];
            #pragma unroll
            for (int rb = 0; rb < 2; rb++) {
                mma16(acc[rb][nt], aF[rb][0], wv.x, wv.y);
                mma16(acc[rb][nt], aF[rb][1], wv.z, wv.w);
            }
        }
    }

    if (EPI == 0) {
        __half* dst = (slice == 0) ? g_qh : (slice == 1) ? g_kh : g_vh;
        float s = (slice == 0) ? scale : 1.0f;   // scale includes log2e for q
        #pragma unroll
        for (int rb = 0; rb < 2; rb++) {
            int r = row0 + wrow * 32 + rb * 16 + lr;
            #pragma unroll
            for (int nt = 0; nt < 4; nt++) {
                int col = (wcol * 4 + nt) * 8 + 2 * lc;
                *(__half2*)&dst[(size_t)r * HID + col] =
                    __floats2half2_rn(acc[rb][nt][0] * s, acc[rb][nt][1] * s);
                *(__half2*)&dst[(size_t)(r + 8) * HID + col] =
                    __floats2half2_rn(acc[rb][nt][2] * s, acc[rb][nt][3] * s);
            }
        }
    } else if (EPI == 1) {
        #pragma unroll
        for (int rb = 0; rb < 2; rb++) {
            int r = row0 + wrow * 32 + rb * 16 + lr;
            #pragma unroll
            for (int nt = 0; nt < 4; nt++) {
                int gcol = slice * 128 + (wcol * 4 + nt) * 8 + 2 * lc;
                float a0 = acc[rb][nt][0], a1 = acc[rb][nt][1];
                float a2 = acc[rb][nt][2], a3 = acc[rb][nt][3];
                a0 = a0 / (1.0f + ex2(-1.702f * LOG2E * a0));
                a1 = a1 / (1.0f + ex2(-1.702f * LOG2E * a1));
                a2 = a2 / (1.0f + ex2(-1.702f * LOG2E * a2));
                a3 = a3 / (1.0f + ex2(-1.702f * LOG2E * a3));
                *(__half2*)&g_ffh[(size_t)r * FF + gcol] = __floats2half2_rn(a0, a1);
                *(__half2*)&g_ffh[(size_t)(r + 8) * FF + gcol] = __floats2half2_rn(a2, a3);
            }
        }
    } else {
        #pragma unroll
        for (int rb = 0; rb < 2; rb++) {
            int r = row0 + wrow * 32 + rb * 16 + lr;
            float s0 = 0.f, q0 = 0.f, s1 = 0.f, q1 = 0.f;
            #pragma unroll
            for (int nt = 0; nt < 4; nt++) {
                int col = (wcol * 4 + nt) * 8 + 2 * lc;
                float2 h0 = *(const float2*)&g_h[(size_t)r * HID + col];
                float2 h1 = *(const float2*)&g_h[(size_t)(r + 8) * HID + col];
                float a0 = acc[rb][nt][0] + h0.x, a1 = acc[rb][nt][1] + h0.y;
                float a2 = acc[rb][nt][2] + h1.x, a3 = acc[rb][nt][3] + h1.y;
                acc[rb][nt][0] = a0; acc[rb][nt][1] = a1;
                acc[rb][nt][2] = a2; acc[rb][nt][3] = a3;
                s0 += a0 + a1; q0 += a0 * a0 + a1 * a1;
                s1 += a2 + a3; q1 += a2 * a2 + a3 * a3;
            }
            #pragma unroll
            for (int o = 1; o <= 2; o <<= 1) {
                s0 += __shfl_xor_sync(0xFFFFFFFFu, s0, o);
                q0 += __shfl_xor_sync(0xFFFFFFFFu, q0, o);
                s1 += __shfl_xor_sync(0xFFFFFFFFu, s1, o);
                q1 += __shfl_xor_sync(0xFFFFFFFFu, q1, o);
            }
            if (lc == 0) {
                int lrow = wrow * 32 + rb * 16 + lr;
                sred[lrow][wcol] = make_float2(s0, q0);
                sred[lrow + 8][wcol] = make_float2(s1, q1);
            }
        }
        __syncthreads();
        #pragma unroll
        for (int rb = 0; rb < 2; rb++) {
            int lrow = wrow * 32 + rb * 16 + lr;
            int r = row0 + lrow;
            float2 t0 = sred[lrow][0], t1 = sred[lrow][1];
            float2 t2 = sred[lrow][2], t3 = sred[lrow][3];
            float S0 = t0.x + t1.x + t2.x + t3.x, Q0 = t0.y + t1.y + t2.y + t3.y;
            float2 u0 = sred[lrow + 8][0], u1 = sred[lrow + 8][1];
            float2 u2 = sred[lrow + 8][2], u3 = sred[lrow + 8][3];
            float S1 = u0.x + u1.x + u2.x + u3.x, Q1 = u0.y + u1.y + u2.y + u3.y;
            float mu0 = S0 * (1.0f / HID);
            float rs0 = rsqrtf(Q0 * (1.0f / HID) - mu0 * mu0 + 1e-12f);
            float mu1 = S1 * (1.0f / HID);
            float rs1 = rsqrtf(Q1 * (1.0f / HID) - mu1 * mu1 + 1e-12f);
            #pragma unroll
            for (int nt = 0; nt < 4; nt++) {
                int col = (wcol * 4 + nt) * 8 + 2 * lc;
                float2 sc = *(const float2*)&lns[col];
                float2 bb = *(const float2*)&lnb[col];
                float o0x = (acc[rb][nt][0] - mu0) * rs0 * sc.x + bb.x;
                float o0y = (acc[rb][nt][1] - mu0) * rs0 * sc.y + bb.y;
                float o1x = (acc[rb][nt][2] - mu1) * rs1 * sc.x + bb.x;
                float o1y = (acc[rb][nt][3] - mu1) * rs1 * sc.y + bb.y;
                *(float2*)&g_h[(size_t)r * HID + col] = make_float2(o0x, o0y);
                *(float2*)&g_h[(size_t)(r + 8) * HID + col] = make_float2(o1x, o1y);
                *(__half2*)&g_hh[(size_t)r * HID + col] = __floats2half2_rn(o0x, o0y);
                *(__half2*)&g_hh[(size_t)(r + 8) * HID + col] = __floats2half2_rn(o1x, o1y);
                if (outp) {
                    if ((r & (Ss - 1)) == Ss - 1)
                        *(float2*)&outp[(r >> 10) * HID + col] = make_float2(o0x, o0y);
                    if (((r + 8) & (Ss - 1)) == Ss - 1)
                        *(float2*)&outp[((r + 8) >> 10) * HID + col] = make_float2(o1x, o1y);
                }
            }
        }
    }
}

// ---- FA2-style fp16 attention, exp2 softmax, 2-stage double buffer ----
__global__ void __launch_bounds__(128) attn_kernel() {
    __shared__ __half sK[2][64][40];
    __shared__ __half sV[2][64][40];

    int qb = blockIdx.x, bh = blockIdx.y;
    int b = bh >> 2, h = bh & 3;
    int tid = threadIdx.x;
    int w = tid >> 5, lane = tid & 31;
    int lr = lane >> 2, lc = lane & 3;

    int cnt = g_bcnt[qb];

    auto prefetch = [&](int ii, int buf) {
        int kb = g_blist[qb * NB + ii];
        #pragma unroll
        for (int i = 0; i < 4; i++) {
            int idx = tid + i * 128;
            int kv = idx >> 8;
            int r = (idx >> 2) & 63, seg = idx & 3;
            const __half* src = (kv ? g_vh : g_kh) +
                (size_t)(b * Ss + kb * BSZ + r) * HID + h * DH + seg * 8;
            cpa16(kv ? &sV[buf][r][seg * 8] : &sK[buf][r][seg * 8], src);
        }
        cpa_commit();
    };

    // fire kb-0 loads first; overlap with Q fragment fetch
    prefetch(0, 0);

    unsigned qf[2][4];
    {
        const __half* qp = g_qh + (size_t)(b * Ss + qb * BSZ + w * 16) * HID + h * DH;
        #pragma unroll
        for (int kc = 0; kc < 2; kc++) {
            qf[kc][0] = *(const unsigned*)&qp[(size_t)lr * HID + kc * 16 + 2 * lc];
            qf[kc][1] = *(const unsigned*)&qp[(size_t)(lr + 8) * HID + kc * 16 + 2 * lc];
            qf[kc][2] = *(const unsigned*)&qp[(size_t)lr * HID + kc * 16 + 2 * lc + 8];
            qf[kc][3] = *(const unsigned*)&qp[(size_t)(lr + 8) * HID + kc * 16 + 2 * lc + 8];
        }
    }

    float o[4][4];
    #pragma unroll
    for (int i = 0; i < 4; i++)
        #pragma unroll
        for (int j = 0; j < 4; j++) o[i][j] = 0.f;
    float ls0 = 0.f, ls1 = 0.f;

    for (int ii = 0; ii < cnt; ii++) {
        int s = ii & 1;
        cpa_wait<0>();
        __syncthreads();
        if (ii + 1 < cnt) prefetch(ii + 1, s ^ 1);

        float sc[8][4];
        #pragma unroll
        for (int nc = 0; nc < 8; nc++) {
            sc[nc][0] = 0.f; sc[nc][1] = 0.f; sc[nc][2] = 0.f; sc[nc][3] = 0.f;
            unsigned r0, r1, r2, r3;
            ldsm4(r0, r1, r2, r3, &sK[s][nc * 8 + (lane & 7)][(lane >> 3) * 8]);
            mma16(sc[nc], qf[0], r0, r1);
            mma16(sc[nc], qf[1], r2, r3);
        }
        #pragma unroll
        for (int kc2 = 0; kc2 < 4; kc2++) {
            // q was pre-scaled by scale*log2(e): exp(s) == ex2(score)
            float e00 = ex2(sc[2*kc2][0]),   e01 = ex2(sc[2*kc2][1]);
            float e02 = ex2(sc[2*kc2][2]),   e03 = ex2(sc[2*kc2][3]);
            float e10 = ex2(sc[2*kc2+1][0]), e11 = ex2(sc[2*kc2+1][1]);
            float e12 = ex2(sc[2*kc2+1][2]), e13 = ex2(sc[2*kc2+1][3]);
            ls0 += e00 + e01 + e10 + e11;
            ls1 += e02 + e03 + e12 + e13;
            unsigned pf[4];
            __half2 p0 = __floats2half2_rn(e00, e01);
            __half2 p1 = __floats2half2_rn(e02, e03);
            __half2 p2 = __floats2half2_rn(e10, e11);
            __half2 p3 = __floats2half2_rn(e12, e13);
            pf[0] = *(unsigned*)&p0; pf[1] = *(unsigned*)&p1;
            pf[2] = *(unsigned*)&p2; pf[3] = *(unsigned*)&p3;
            unsigned r0, r1, r2, r3;
            const __half* vbase = &sV[s][kc2 * 16 + ((lane >> 3) & 1) * 8 + (lane & 7)][0];
            ldsm4t(r0, r1, r2, r3, vbase + (lane >> 4) * 8);
            mma16(o[0], pf, r0, r1);
            mma16(o[1], pf, r2, r3);
            ldsm4t(r0, r1, r2, r3, vbase + (lane >> 4) * 8 + 16);
            mma16(o[2], pf, r0, r1);
            mma16(o[3], pf, r2, r3);
        }
    }

    ls0 += __shfl_xor_sync(0xFFFFFFFFu, ls0, 1);
    ls0 += __shfl_xor_sync(0xFFFFFFFFu, ls0, 2);
    ls1 += __shfl_xor_sync(0xFFFFFFFFu, ls1, 1);
    ls1 += __shfl_xor_sync(0xFFFFFFFFu, ls1, 2);
    float inv0 = 1.0f / ls0, inv1 = 1.0f / ls1;

    int r0 = b * Ss + qb * BSZ + w * 16 + lr;
    __half* c0 = &g_ctxh[(size_t)r0 * HID + h * DH];
    __half* c1 = &g_ctxh[(size_t)(r0 + 8) * HID + h * DH];
    #pragma unroll
    for (int nt = 0; nt < 4; nt++) {
        *(__half2*)&c0[nt * 8 + 2 * lc] = __floats2half2_rn(o[nt][0] * inv0, o[nt][1] * inv0);
        *(__half2*)&c1[nt * 8 + 2 * lc] = __floats2half2_rn(o[nt][2] * inv1, o[nt][3] * inv1);
    }
}

extern "C" void kernel_launch(void* const* d_in, const int* in_sizes, int n_in,
                              void* d_out, int out_size) {
    const float* x       = (const float*)d_in[0];
    const float* token_w = (const float*)d_in[1];
    const float* token_b = (const float*)d_in[2];
    const float* pos_emb = (const float*)d_in[3];
    const float* mpos    = (const float*)d_in[4];
    const float* type_e  = (const float*)d_in[5];
    const float* elns    = (const float*)d_in[6];
    const float* elnb    = (const float*)d_in[7];
    const float* Wq      = (const float*)d_in[8];
    const float* bq      = (const float*)d_in[9];
    const float* Wk      = (const float*)d_in[10];
    const float* bk      = (const float*)d_in[11];
    const float* Wv      = (const float*)d_in[12];
    const float* bv      = (const float*)d_in[13];
    const float* Wo      = (const float*)d_in[14];
    const float* bo      = (const float*)d_in[15];
    const float* ln1s    = (const float*)d_in[16];
    const float* ln1b    = (const float*)d_in[17];
    const float* W1      = (const float*)d_in[18];
    const float* b1      = (const float*)d_in[19];
    const float* W2      = (const float*)d_in[20];
    const float* b2      = (const float*)d_in[21];
    const float* ln2s    = (const float*)d_in[22];
    const float* ln2b    = (const float*)d_in[23];
    const unsigned char* mask = (const unsigned char*)d_in[24];

    wconv_kernel<<<dim3(74, 6 * LL), 256>>>(Wq, Wk, Wv, Wo, W1, W2, mask);
    embed_kernel<<<NROWS / 8, 256>>>(x, token_w, token_b, pos_emb, mpos, type_e, elns, elnb);

    const float qscale = (1.0f / sqrtf((float)DH)) * LOG2E;  // fold log2e into q
    for (int l = 0; l < LL; l++) {
        gemm_kernel<128, 0, 0><<<dim3(NROWS / 64, 3), 256>>>(
            l, qscale, bq + l * HID, bk + l * HID, bv + l * HID, 0, 0, 0);
        attn_kernel<<<dim3(NB, Bb * HEADS), 128>>>();
        gemm_kernel<128, 2, 1><<<dim3(NROWS / 64, 1), 256>>>(
            l, 1.f, bo + l * HID, 0, 0, ln1s + l * HID, ln1b + l * HID, 0);
        gemm_kernel<128, 1, 0><<<dim3(NROWS / 64, 2), 256>>>(
            l, 1.f, b1 + l * FF, 0, 0, 0, 0, 0);
        gemm_kernel<256, 2, 2><<<dim3(NROWS / 64, 1), 256>>>(
            l, 1.f, b2 + l * HID, 0, 0, ln2s + l * HID, ln2b + l * HID,
            (l == LL - 1) ? (float*)d_out : 0);
    }
}